// round 3
// baseline (speedup 1.0000x reference)
#include <cuda_runtime.h>

// Problem constants
#define BB 32
#define CC 256
#define HH 32
#define WW 32
#define NE 1024
#define NG 8
#define CPG 128   // codes per group
#define WPG 4     // w positions per group

#define ZQ_ELEMS  (BB*CC*HH*WW)          // 8388608
#define LOSS_OFF  (ZQ_ELEMS)             // loss, commitment, codebook
#define IDX_OFF   (ZQ_ELEMS + 3)         // 32768 indices as float
#define MEAN_DEN  ((double)ZQ_ELEMS)

__device__ float  g_codebook[NE*CC];
__device__ float  g_cnorm[NE];
__device__ double g_sqsum;

// ---------------------------------------------------------------------------
// Kernel 1: codebook = emb @ proj^T (sequential ascending-k fma chain per
// element, matching Eigen/cublas SGEMM accumulation), code norms, zero loss.
// Grid: 32 blocks x 256 threads, each block does 32 codebook rows.
// ---------------------------------------------------------------------------
__global__ void prep_kernel(const float* __restrict__ emb,
                            const float* __restrict__ proj) {
    __shared__ float es[32*CC];
    __shared__ float red[256];
    int tid = threadIdx.x;
    int j0 = blockIdx.x * 32;

    for (int i = tid; i < 32*CC; i += 256) es[i] = emb[j0*CC + i];
    __syncthreads();

    int i = tid;          // output column
    float acc[32];
    #pragma unroll
    for (int j = 0; j < 32; j++) acc[j] = 0.f;

    for (int k = 0; k < CC; k++) {           // ascending k, single accumulator
        float p = proj[i*CC + k];
        #pragma unroll
        for (int j = 0; j < 32; j++)
            acc[j] = fmaf(es[j*CC + k], p, acc[j]);
    }
    #pragma unroll
    for (int j = 0; j < 32; j++)
        g_codebook[(size_t)(j0 + j)*CC + i] = acc[j];

    // code norms (order-insensitive at this magnitude): tree reduce
    for (int j = 0; j < 32; j++) {
        red[tid] = acc[j]*acc[j];
        __syncthreads();
        for (int s = 128; s > 0; s >>= 1) {
            if (tid < s) red[tid] += red[tid + s];
            __syncthreads();
        }
        if (tid == 0) g_cnorm[j0 + j] = red[0];
        __syncthreads();
    }

    if (blockIdx.x == 0 && tid == 0) g_sqsum = 0.0;
}

// ---------------------------------------------------------------------------
// Kernel 2: main. Grid (16 chunks, 8 groups) x 256 threads.
// Each block: group codebook in smem (padded 257), 256 tokens in 4 passes of
// 64.  znorm per token computed ONCE per block with the reference's exact
// sequential mul+add chain.  Per warp: 8 tokens x 4 codes/lane register tile.
// ---------------------------------------------------------------------------
extern __shared__ float smem[];

__global__ __launch_bounds__(256, 1)
void main_kernel(const float* __restrict__ z, float* __restrict__ out) {
    float* cbs = smem;                       // [128][257]
    float* cn  = smem + CPG*257;             // [128]
    float* zs  = cn + CPG;                   // [64][256]
    float* znorm_s = zs + 64*CC;             // [256]  (token = pass*64 + loc)
    __shared__ int    sel[64];
    __shared__ double wsum[8];

    int g     = blockIdx.y;
    int chunk = blockIdx.x;                  // 0..15
    int tid   = threadIdx.x;
    int lane  = tid & 31;
    int warp  = tid >> 5;
    int w0    = g * WPG;

    // stage group codebook + norms
    const float* cbg = g_codebook + (size_t)g*CPG*CC;
    for (int i = tid; i < CPG*CC; i += 256) {
        int j = i >> 8, c = i & 255;
        cbs[j*257 + c] = cbg[i];
    }
    if (tid < CPG) cn[tid] = g_cnorm[g*CPG + tid];

    // ---- znorm: one token per thread, reference-exact sequential chain ----
    // token tid -> pass = tid>>6, loc = tid&63, rl = loc>>2, wi = loc&3
    {
        int pass = tid >> 6;
        int loc  = tid & 63;
        int rl   = loc >> 2;
        int wi   = loc & 3;
        int bh = chunk*64 + pass*16 + rl;
        int b = bh >> 5, h = bh & 31;
        const float* zp = z + (size_t)b*262144 + (size_t)h*32 + w0 + wi;
        float acc = 0.f;
        #pragma unroll 8
        for (int c = 0; c < CC; c++) {
            float v = zp[(size_t)c*1024];
            acc = __fadd_rn(acc, __fmul_rn(v, v));   // rounded mul, rounded add
        }
        znorm_s[tid] = acc;
    }
    __syncthreads();

    double lsum = 0.0;

    for (int pass = 0; pass < 4; pass++) {
        int bh0 = chunk*64 + pass*16;        // 16 (b,h) rows per pass

        // ---- load 64 tokens (16 bh rows x 4 w) into zs ----
        for (int rr = 0; rr < 2; rr++) {
            int rl = warp + rr*8;            // 0..15
            int bh = bh0 + rl;
            int b = bh >> 5, h = bh & 31;
            const float4* src = (const float4*)(z + (size_t)b*262144 + (size_t)h*32 + w0);
            #pragma unroll
            for (int k = 0; k < 8; k++) {
                int c = lane + 32*k;
                float4 v = src[(size_t)c*256];   // z[b,c,h,w0..w0+3]
                zs[(rl*4+0)*256 + c] = v.x;
                zs[(rl*4+1)*256 + c] = v.y;
                zs[(rl*4+2)*256 + c] = v.z;
                zs[(rl*4+3)*256 + c] = v.w;
            }
        }
        __syncthreads();

        // ---- dot products: warp handles tokens warp*8..warp*8+7 ----
        // single accumulator per (code, token), ascending c: matches
        // Eigen/cublas sequential fma chain bit-exactly.
        float acc[4][8];
        #pragma unroll
        for (int q = 0; q < 4; q++)
            #pragma unroll
            for (int t = 0; t < 8; t++) acc[q][t] = 0.f;

        const float* zrow = zs + (warp*8)*256;
        const float* cb   = cbs + lane*257;

        #pragma unroll 4
        for (int c = 0; c < CC; c++) {
            float c0 = cb[c];
            float c1 = cb[32*257 + c];
            float c2 = cb[64*257 + c];
            float c3 = cb[96*257 + c];
            #pragma unroll
            for (int t = 0; t < 8; t++) {
                float zv = zrow[t*256 + c];
                acc[0][t] = fmaf(c0, zv, acc[0][t]);
                acc[1][t] = fmaf(c1, zv, acc[1][t]);
                acc[2][t] = fmaf(c2, zv, acc[2][t]);
                acc[3][t] = fmaf(c3, zv, acc[3][t]);
            }
        }

        // ---- reference-exact distance + first-min argmin ----
        #pragma unroll
        for (int t = 0; t < 8; t++) {
            float zn = znorm_s[pass*64 + warp*8 + t];
            float best;
            int   bj;
            {
                float s0 = __fadd_rn(zn, cn[lane]);                    // fl(zn + cn)
                best = __fsub_rn(s0, __fadd_rn(acc[0][t], acc[0][t])); // fl(s - 2dot)
                bj   = lane;
            }
            #pragma unroll
            for (int q = 1; q < 4; q++) {
                int   j  = lane + 32*q;
                float sq = __fadd_rn(zn, cn[j]);
                float v  = __fsub_rn(sq, __fadd_rn(acc[q][t], acc[q][t]));
                if (v < best || (v == best && j < bj)) { best = v; bj = j; }
            }
            #pragma unroll
            for (int off = 16; off; off >>= 1) {
                float ov = __shfl_down_sync(0xffffffffu, best, off);
                int   oj = __shfl_down_sync(0xffffffffu, bj,   off);
                if (ov < best || (ov == best && oj < bj)) { best = ov; bj = oj; }
            }
            if (lane == 0) sel[warp*8 + t] = bj;
        }
        __syncthreads();

        // ---- write zq (strided float4), accumulate (zq - z)^2 ----
        for (int rr = 0; rr < 2; rr++) {
            int rl = warp + rr*8;
            int bh = bh0 + rl;
            int b = bh >> 5, h = bh & 31;
            float4* dst = (float4*)(out + (size_t)b*262144 + (size_t)h*32 + w0);
            int s0 = sel[rl*4+0], s1 = sel[rl*4+1], s2 = sel[rl*4+2], s3 = sel[rl*4+3];
            #pragma unroll
            for (int k = 0; k < 8; k++) {
                int c = lane + 32*k;
                float4 v;
                v.x = cbs[s0*257 + c];
                v.y = cbs[s1*257 + c];
                v.z = cbs[s2*257 + c];
                v.w = cbs[s3*257 + c];
                dst[(size_t)c*256] = v;
                float d0 = v.x - zs[(rl*4+0)*256 + c];
                float d1 = v.y - zs[(rl*4+1)*256 + c];
                float d2 = v.z - zs[(rl*4+2)*256 + c];
                float d3 = v.w - zs[(rl*4+3)*256 + c];
                lsum += (double)(d0*d0) + (double)(d1*d1)
                      + (double)(d2*d2) + (double)(d3*d3);
            }
        }

        // ---- idx output (as float) ----
        if (tid < 64) {
            int bh = bh0 + (tid >> 2);
            int wi = tid & 3;
            int b = bh >> 5, h = bh & 31;
            out[IDX_OFF + b*1024 + h*32 + w0 + wi] = (float)(g*CPG + sel[tid]);
        }
        __syncthreads();   // protect zs/sel reuse next pass
    }

    // block-reduce the squared-diff sum, one atomic per block
    #pragma unroll
    for (int off = 16; off; off >>= 1)
        lsum += __shfl_down_sync(0xffffffffu, lsum, off);
    if (lane == 0) wsum[warp] = lsum;
    __syncthreads();
    if (warp == 0) {
        double v = (lane < 8) ? wsum[lane] : 0.0;
        #pragma unroll
        for (int off = 4; off; off >>= 1)
            v += __shfl_down_sync(0xffffffffu, v, off);
        if (lane == 0) atomicAdd(&g_sqsum, v);
    }
}

// ---------------------------------------------------------------------------
// Kernel 3: finalize losses
// ---------------------------------------------------------------------------
__global__ void fin_kernel(float* __restrict__ out) {
    double M = g_sqsum / MEAN_DEN;           // mean((zq - zc)^2)
    out[LOSS_OFF + 0] = (float)(1.25 * M);   // loss
    out[LOSS_OFF + 1] = (float)(0.25 * M);   // commitment_loss
    out[LOSS_OFF + 2] = (float)M;            // codebook_loss
}

// ---------------------------------------------------------------------------
extern "C" void kernel_launch(void* const* d_in, const int* in_sizes, int n_in,
                              void* d_out, int out_size) {
    const float *z = nullptr, *emb = nullptr, *proj = nullptr;
    for (int i = 0; i < n_in; i++) {
        if (in_sizes[i] == ZQ_ELEMS)      z    = (const float*)d_in[i];
        else if (in_sizes[i] == NE*CC)    emb  = (const float*)d_in[i];
        else if (in_sizes[i] == CC*CC)    proj = (const float*)d_in[i];
    }
    float* out = (float*)d_out;

    const int SMEM_BYTES = (CPG*257 + CPG + 64*CC + 256) * (int)sizeof(float); // 198,656
    cudaFuncSetAttribute(main_kernel,
                         cudaFuncAttributeMaxDynamicSharedMemorySize, SMEM_BYTES);

    prep_kernel<<<32, 256>>>(emb, proj);
    main_kernel<<<dim3(16, 8), 256, SMEM_BYTES>>>(z, out);
    fin_kernel<<<1, 1>>>(out);
}

// round 4
// speedup vs baseline: 1.5121x; 1.5121x over previous
#include <cuda_runtime.h>

// Problem constants
#define BB 32
#define CC 256
#define HH 32
#define WW 32
#define NE 1024
#define NG 8
#define CPG 128   // codes per group
#define WPG 4     // w positions per group

#define ZQ_ELEMS  (BB*CC*HH*WW)          // 8388608
#define LOSS_OFF  (ZQ_ELEMS)             // loss, commitment, codebook
#define IDX_OFF   (ZQ_ELEMS + 3)         // 32768 indices as float
#define MEAN_DEN  ((double)ZQ_ELEMS)

#define ZT_STRIDE 66                     // zs_t row stride (floats): 64 tokens + 2 pad

__device__ float  g_codebook[NE*CC];
__device__ float  g_cnorm[NE];
__device__ double g_sqsum;

typedef unsigned long long ull;

__device__ __forceinline__ void ffma2(ull& acc, ull a, ull b) {
    asm("fma.rn.f32x2 %0, %1, %2, %0;" : "+l"(acc) : "l"(a), "l"(b));
}
__device__ __forceinline__ ull dup2(float x) {
    ull r; unsigned u = __float_as_uint(x);
    asm("mov.b64 %0, {%1, %1};" : "=l"(r) : "r"(u));
    return r;
}
__device__ __forceinline__ float lo32(ull v) { return __uint_as_float((unsigned)v); }
__device__ __forceinline__ float hi32(ull v) { return __uint_as_float((unsigned)(v >> 32)); }

// ---------------------------------------------------------------------------
// Kernel 1: codebook = emb @ proj^T (sequential ascending-k fma chain per
// element — bit-exact requirement), code norms, zero the loss accumulator.
// Grid: 128 blocks x 256 threads, each block does 8 codebook rows.
// ---------------------------------------------------------------------------
__global__ __launch_bounds__(256)
void prep_kernel(const float* __restrict__ emb,
                 const float* __restrict__ proj) {
    __shared__ float es[8*CC];
    __shared__ float part[8][9];         // [j][warp]
    int tid  = threadIdx.x;
    int lane = tid & 31;
    int warp = tid >> 5;
    int j0   = blockIdx.x * 8;

    for (int i = tid; i < 8*CC; i += 256) es[i] = emb[j0*CC + i];
    __syncthreads();

    int i = tid;          // output column
    float acc[8];
    #pragma unroll
    for (int j = 0; j < 8; j++) acc[j] = 0.f;

    const float4* pv = (const float4*)(proj + (size_t)i*CC);
    #pragma unroll 4
    for (int k4 = 0; k4 < CC/4; k4++) {
        float4 p = pv[k4];
        int k = k4*4;
        #pragma unroll
        for (int j = 0; j < 8; j++) acc[j] = fmaf(es[j*CC + k+0], p.x, acc[j]);
        #pragma unroll
        for (int j = 0; j < 8; j++) acc[j] = fmaf(es[j*CC + k+1], p.y, acc[j]);
        #pragma unroll
        for (int j = 0; j < 8; j++) acc[j] = fmaf(es[j*CC + k+2], p.z, acc[j]);
        #pragma unroll
        for (int j = 0; j < 8; j++) acc[j] = fmaf(es[j*CC + k+3], p.w, acc[j]);
    }
    #pragma unroll
    for (int j = 0; j < 8; j++)
        g_codebook[(size_t)(j0 + j)*CC + i] = acc[j];

    // code norms: order-insensitive at this magnitude -> shfl tree reduce
    #pragma unroll
    for (int j = 0; j < 8; j++) {
        float v = acc[j]*acc[j];
        #pragma unroll
        for (int off = 16; off; off >>= 1)
            v += __shfl_down_sync(0xffffffffu, v, off);
        if (lane == 0) part[j][warp] = v;
    }
    __syncthreads();
    if (tid < 8) {
        float s = 0.f;
        #pragma unroll
        for (int w = 0; w < 8; w++) s += part[tid][w];
        g_cnorm[j0 + tid] = s;
    }
    if (blockIdx.x == 0 && tid == 0) g_sqsum = 0.0;
}

// ---------------------------------------------------------------------------
// Kernel 2: main. Grid (16 chunks, 8 groups) x 256 threads.
// Per block: group codebook in smem ([128][257], conflict-free scalar reads),
// 256 tokens in 4 passes of 64.  z staged token-major zs_t[c][66].
// Per warp: 8 tokens x 4 codes/lane, FFMA2 over token pairs.
// ---------------------------------------------------------------------------
extern __shared__ float smem[];

__global__ __launch_bounds__(256, 1)
void main_kernel(const float* __restrict__ z, float* __restrict__ out) {
    float* cbs  = smem;                        // [128][257]
    float* cn   = cbs + CPG*257;               // [128]
    float* zs_t = cn + CPG;                    // [256][66]  token-major
    float* znorm_s = zs_t + CC*ZT_STRIDE;      // [64]
    __shared__ int    sel[64];
    __shared__ double wsum[8];

    int g     = blockIdx.y;
    int chunk = blockIdx.x;                    // 0..15
    int tid   = threadIdx.x;
    int lane  = tid & 31;
    int warp  = tid >> 5;
    int w0    = g * WPG;

    // stage group codebook + norms
    const float* cbg = g_codebook + (size_t)g*CPG*CC;
    for (int i = tid; i < CPG*CC; i += 256) {
        int j = i >> 8, c = i & 255;
        cbs[j*257 + c] = cbg[i];
    }
    if (tid < CPG) cn[tid] = g_cnorm[g*CPG + tid];
    __syncthreads();

    double lsum = 0.0;

    for (int pass = 0; pass < 4; pass++) {
        int bh0 = chunk*64 + pass*16;          // 16 (b,h) rows per pass

        // ---- stage 64 tokens token-major: zs_t[c*66 + tok], tok = rl*4+wi ----
        for (int rr = 0; rr < 2; rr++) {
            int rl = warp + rr*8;              // 0..15
            int bh = bh0 + rl;
            int b = bh >> 5, h = bh & 31;
            const float4* src = (const float4*)(z + (size_t)b*262144 + (size_t)h*32 + w0);
            #pragma unroll
            for (int k = 0; k < 8; k++) {
                int c = lane + 32*k;
                float4 v = src[(size_t)c*256];     // z[b,c,h,w0..w0+3]
                float2* d = (float2*)(zs_t + c*ZT_STRIDE + rl*4);
                d[0] = make_float2(v.x, v.y);
                d[1] = make_float2(v.z, v.w);
            }
        }
        __syncthreads();

        // ---- znorm: reference-exact sequential chain, one thread per token ----
        if (tid < 64) {
            float acc = 0.f;
            #pragma unroll 8
            for (int c = 0; c < CC; c++) {
                float v = zs_t[c*ZT_STRIDE + tid];
                acc = __fadd_rn(acc, __fmul_rn(v, v));
            }
            znorm_s[tid] = acc;
        }
        __syncthreads();

        // ---- dot products via FFMA2: warp owns tokens warp*8..warp*8+7 ----
        // acc2[q][p]: code lane+32q, token pair (2p, 2p+1); each half is a
        // single sequential ascending-c fma chain (bit-exact).
        ull acc2[4][4];
        #pragma unroll
        for (int q = 0; q < 4; q++)
            #pragma unroll
            for (int p = 0; p < 4; p++) acc2[q][p] = 0ull;

        const float* cb = cbs + lane*257;
        const float* zbase = zs_t + warp*8;

        #pragma unroll 4
        for (int c = 0; c < CC; c++) {
            ull d0 = dup2(cb[c]);
            ull d1 = dup2(cb[32*257 + c]);
            ull d2 = dup2(cb[64*257 + c]);
            ull d3 = dup2(cb[96*257 + c]);
            const ull* zp = (const ull*)(zbase + c*ZT_STRIDE);
            ull z0 = zp[0], z1 = zp[1], z2 = zp[2], z3 = zp[3];
            ffma2(acc2[0][0], d0, z0); ffma2(acc2[0][1], d0, z1);
            ffma2(acc2[0][2], d0, z2); ffma2(acc2[0][3], d0, z3);
            ffma2(acc2[1][0], d1, z0); ffma2(acc2[1][1], d1, z1);
            ffma2(acc2[1][2], d1, z2); ffma2(acc2[1][3], d1, z3);
            ffma2(acc2[2][0], d2, z0); ffma2(acc2[2][1], d2, z1);
            ffma2(acc2[2][2], d2, z2); ffma2(acc2[2][3], d2, z3);
            ffma2(acc2[3][0], d3, z0); ffma2(acc2[3][1], d3, z1);
            ffma2(acc2[3][2], d3, z2); ffma2(acc2[3][3], d3, z3);
        }

        // ---- reference-exact distance + first-min argmin ----
        #pragma unroll
        for (int p = 0; p < 4; p++) {
            #pragma unroll
            for (int e = 0; e < 2; e++) {
                int t = 2*p + e;
                float zn = znorm_s[warp*8 + t];
                float best; int bj;
                {
                    float dot = e ? hi32(acc2[0][p]) : lo32(acc2[0][p]);
                    float s0  = __fadd_rn(zn, cn[lane]);
                    best = __fsub_rn(s0, __fadd_rn(dot, dot));
                    bj   = lane;
                }
                #pragma unroll
                for (int q = 1; q < 4; q++) {
                    int   j   = lane + 32*q;
                    float dot = e ? hi32(acc2[q][p]) : lo32(acc2[q][p]);
                    float sq  = __fadd_rn(zn, cn[j]);
                    float v   = __fsub_rn(sq, __fadd_rn(dot, dot));
                    if (v < best || (v == best && j < bj)) { best = v; bj = j; }
                }
                #pragma unroll
                for (int off = 16; off; off >>= 1) {
                    float ov = __shfl_down_sync(0xffffffffu, best, off);
                    int   oj = __shfl_down_sync(0xffffffffu, bj,   off);
                    if (ov < best || (ov == best && oj < bj)) { best = ov; bj = oj; }
                }
                if (lane == 0) sel[warp*8 + t] = bj;
            }
        }
        __syncthreads();

        // ---- write zq (strided float4), accumulate (zq - z)^2 ----
        for (int rr = 0; rr < 2; rr++) {
            int rl = warp + rr*8;
            int bh = bh0 + rl;
            int b = bh >> 5, h = bh & 31;
            float4* dst = (float4*)(out + (size_t)b*262144 + (size_t)h*32 + w0);
            int s0 = sel[rl*4+0], s1 = sel[rl*4+1], s2 = sel[rl*4+2], s3 = sel[rl*4+3];
            #pragma unroll
            for (int k = 0; k < 8; k++) {
                int c = lane + 32*k;
                float4 v;
                v.x = cbs[s0*257 + c];
                v.y = cbs[s1*257 + c];
                v.z = cbs[s2*257 + c];
                v.w = cbs[s3*257 + c];
                dst[(size_t)c*256] = v;
                float2 za = *(const float2*)(zs_t + c*ZT_STRIDE + rl*4);
                float2 zb = *(const float2*)(zs_t + c*ZT_STRIDE + rl*4 + 2);
                float d0 = v.x - za.x;
                float d1 = v.y - za.y;
                float d2 = v.z - zb.x;
                float d3 = v.w - zb.y;
                lsum += (double)(d0*d0) + (double)(d1*d1)
                      + (double)(d2*d2) + (double)(d3*d3);
            }
        }

        // ---- idx output (as float) ----
        if (tid < 64) {
            int bh = bh0 + (tid >> 2);
            int wi = tid & 3;
            int b = bh >> 5, h = bh & 31;
            out[IDX_OFF + b*1024 + h*32 + w0 + wi] = (float)(g*CPG + sel[tid]);
        }
        __syncthreads();   // protect zs_t/sel reuse next pass
    }

    // block-reduce the squared-diff sum, one atomic per block
    #pragma unroll
    for (int off = 16; off; off >>= 1)
        lsum += __shfl_down_sync(0xffffffffu, lsum, off);
    if (lane == 0) wsum[warp] = lsum;
    __syncthreads();
    if (warp == 0) {
        double v = (lane < 8) ? wsum[lane] : 0.0;
        #pragma unroll
        for (int off = 4; off; off >>= 1)
            v += __shfl_down_sync(0xffffffffu, v, off);
        if (lane == 0) atomicAdd(&g_sqsum, v);
    }
}

// ---------------------------------------------------------------------------
// Kernel 3: finalize losses
// ---------------------------------------------------------------------------
__global__ void fin_kernel(float* __restrict__ out) {
    double M = g_sqsum / MEAN_DEN;           // mean((zq - zc)^2)
    out[LOSS_OFF + 0] = (float)(1.25 * M);   // loss
    out[LOSS_OFF + 1] = (float)(0.25 * M);   // commitment_loss
    out[LOSS_OFF + 2] = (float)M;            // codebook_loss
}

// ---------------------------------------------------------------------------
extern "C" void kernel_launch(void* const* d_in, const int* in_sizes, int n_in,
                              void* d_out, int out_size) {
    const float *z = nullptr, *emb = nullptr, *proj = nullptr;
    for (int i = 0; i < n_in; i++) {
        if (in_sizes[i] == ZQ_ELEMS)      z    = (const float*)d_in[i];
        else if (in_sizes[i] == NE*CC)    emb  = (const float*)d_in[i];
        else if (in_sizes[i] == CC*CC)    proj = (const float*)d_in[i];
    }
    float* out = (float*)d_out;

    const int SMEM_BYTES = (CPG*257 + CPG + CC*ZT_STRIDE + 64) * (int)sizeof(float); // 199,936
    cudaFuncSetAttribute(main_kernel,
                         cudaFuncAttributeMaxDynamicSharedMemorySize, SMEM_BYTES);

    prep_kernel<<<128, 256>>>(emb, proj);
    main_kernel<<<dim3(16, 8), 256, SMEM_BYTES>>>(z, out);
    fin_kernel<<<1, 1>>>(out);
}